// round 13
// baseline (speedup 1.0000x reference)
#include <cuda_runtime.h>
#include <cuda_fp16.h>
#include <cstdint>

// Problem constants
#define B_    4
#define L_    1024
#define FP_   32
#define DP_   8
#define F_    32
#define D_    16
#define K_    3
#define W_    1022            // L - K + 1
#define N_    96              // K * FP
#define WB_   4088            // W * B
#define COLS_ 512             // F * D
#define UH_PER_WB 49152       // N * COLS
#define GRID_ 148             // persistent CTAs

// Global scratch for u_hat in fp16: 4088 * 49152 * 2B = 401.8 MB
__device__ __half g_uhat[(size_t)WB_ * UH_PER_WB];

// ---------------------------------------------------------------------------
// Phase 1: u_hat[wb, n, col] = bias[n,col] + sum_d x[b,w+k,fp,d] * W[n,f,d,e]
// Grid (n=96, tile=32), 256 threads; 2 cols/thread, row-pairs via fma.rn.f32x2.
// ---------------------------------------------------------------------------
__global__ __launch_bounds__(256) void uhat_kernel(const float* __restrict__ x,
                                                   const float* __restrict__ wgt,
                                                   const float* __restrict__ bias)
{
    const int n    = blockIdx.x;      // 0..95
    const int tile = blockIdx.y;      // 0..31
    const int t    = threadIdx.x;
    const int k    = n >> 5;
    const int fp   = n & 31;

    __shared__ float xsT[DP_][128];   // transposed: xsT[d][r]

    {
        int r = t >> 1, q = t & 1;
        int wb = tile * 128 + r;
        float4 v = make_float4(0.f, 0.f, 0.f, 0.f);
        if (wb < WB_) {
            int w = wb >> 2, b = wb & 3;
            const float* p = x + ((size_t)b * (L_ * FP_ * DP_)
                                  + (size_t)(w + k) * (FP_ * DP_)
                                  + fp * DP_ + q * 4);
            v = *(const float4*)p;
        }
        xsT[q * 4 + 0][r] = v.x;
        xsT[q * 4 + 1][r] = v.y;
        xsT[q * 4 + 2][r] = v.z;
        xsT[q * 4 + 3][r] = v.w;
    }

    const int c0 = 2 * t;
    const int f  = c0 >> 4;
    const int e0 = c0 & 15;
    unsigned long long wd0[DP_], wd1[DP_];
    const float* wp = wgt + (size_t)n * (F_ * DP_ * D_) + f * (DP_ * D_) + e0;
#pragma unroll
    for (int d = 0; d < DP_; d++) {
        float2 w2 = *(const float2*)(wp + d * D_);
        asm("mov.b64 %0, {%1, %1};" : "=l"(wd0[d]) : "f"(w2.x));
        asm("mov.b64 %0, {%1, %1};" : "=l"(wd1[d]) : "f"(w2.y));
    }
    float2 bz = *(const float2*)(bias + (size_t)n * COLS_ + c0);
    unsigned long long bia, bib;
    asm("mov.b64 %0, {%1, %1};" : "=l"(bia) : "f"(bz.x));
    asm("mov.b64 %0, {%1, %1};" : "=l"(bib) : "f"(bz.y));

    __syncthreads();

    const int wb0 = tile * 128;
#pragma unroll 1
    for (int r = 0; r < 128; r += 2) {
        unsigned long long acc0 = bia, acc1 = bib;
#pragma unroll
        for (int d = 0; d < DP_; d++) {
            unsigned long long xp = *(const unsigned long long*)&xsT[d][r];
            asm("fma.rn.f32x2 %0, %1, %2, %0;" : "+l"(acc0) : "l"(xp), "l"(wd0[d]));
            asm("fma.rn.f32x2 %0, %1, %2, %0;" : "+l"(acc1) : "l"(xp), "l"(wd1[d]));
        }
        float lo0, hi0, lo1, hi1;
        asm("mov.b64 {%0, %1}, %2;" : "=f"(lo0), "=f"(hi0) : "l"(acc0));
        asm("mov.b64 {%0, %1}, %2;" : "=f"(lo1), "=f"(hi1) : "l"(acc1));
        int wbA = wb0 + r, wbB = wb0 + r + 1;
        if (wbA < WB_)
            *(__half2*)&g_uhat[(size_t)wbA * UH_PER_WB + (size_t)n * COLS_ + c0]
                = __floats2half2_rn(lo0, lo1);
        if (wbB < WB_)
            *(__half2*)&g_uhat[(size_t)wbB * UH_PER_WB + (size_t)n * COLS_ + c0]
                = __floats2half2_rn(hi0, hi1);
    }
}

// ---------------------------------------------------------------------------
// Phase 2: persistent routing, 148 CTAs x 1024 threads (32 warps), double-
// buffered fp16 tile via cp.async. Warp w owns rows 3w..3w+2, register-cached
// (single tile traversal, R12 design). New in R13:
//   - squash-norm accumulated by atomicAdd into double-buffered snrm[2][32]
//     inside the reduce phase; squash scale computed inline by consumers
//     -> the 3 serial t<32 phases and 3 __syncthreads per tile are gone.
//   - snrm zeroing folded into compute phases (warp 31).
// Phase->snrm buffer: init->0, round0 reads 0 writes 1, round1 reads 1
// writes 0, output reads 0.
// smem (bytes): su0[98304] su1[98304] sph[32768] svT[2048] snrm[256] = 231680
// ---------------------------------------------------------------------------
#define OFF_SU0   0
#define OFF_SU1   98304
#define OFF_SPH   196608
#define OFF_SVT   229376
#define OFF_SNRM  231424
#define SMEM_TOTAL 231680

// 1024 threads x 16B x LOAD_ITERS = 98304 bytes per tile
#define LOAD_ITERS 6

__device__ __forceinline__ float squash_scale(float nrm)
{
    nrm = fmaxf(nrm, 1e-30f);
    return nrm / (1.f + nrm) * rsqrtf(nrm);
}

__global__ __launch_bounds__(1024, 1) void routing_kernel(float* __restrict__ out)
{
    extern __shared__ __align__(16) unsigned char smem[];
    float*   svT  = (float*)(smem + OFF_SVT);   // [16][32] : svT[e*32+f] (raw s)
    float*   snrm = (float*)(smem + OFF_SNRM);  // [2][32] |s|^2 per f, dbl-buffered
    __half2* sph  = (__half2*)(smem + OFF_SPH); // partials [32 warps][8 e2][32 f]

    const int t   = threadIdx.x;
    const int bid = blockIdx.x;
    const uint32_t smem_u32 = (uint32_t)__cvta_generic_to_shared(smem);

    auto issue_load = [&](int wb, int bufsel) {
        const char* src = (const char*)(g_uhat + (size_t)wb * UH_PER_WB) + t * 16;
        uint32_t dst = smem_u32 + (bufsel ? OFF_SU1 : OFF_SU0) + t * 16;
#pragma unroll
        for (int i = 0; i < LOAD_ITERS; i++) {
            asm volatile("cp.async.cg.shared.global [%0], [%1], 16;"
                         :: "r"(dst + i * 16384), "l"(src + (size_t)i * 16384));
        }
        asm volatile("cp.async.commit_group;");
    };

    issue_load(bid, 0);
    int buf = 0;

    const int l    = t & 31, wrp = t >> 5;   // lane = f, warp owns rows 3w..3w+2
    const int row0 = wrp * 3;
    const int fR   = t & 31, e2R = t >> 5;   // reduce mapping (valid when t<256)

    for (int wb = bid; wb < WB_; wb += GRID_) {
        const int nxt = wb + GRID_;
        if (nxt < WB_) {
            issue_load(nxt, buf ^ 1);
            asm volatile("cp.async.wait_group 1;" ::: "memory");
        } else {
            asm volatile("cp.async.wait_group 0;" ::: "memory");
        }
        __syncthreads();

        const __half* suh = (const __half*)(smem + (buf ? OFF_SU1 : OFF_SU0));

        // ---- load my 3 rows ONCE, packed half2 (lane l = f slice, 16 halves)
        uint4 rA[3], rB[3];
#pragma unroll
        for (int r = 0; r < 3; r++) {
            const uint4* p = (const uint4*)(suh + (row0 + r) * 512 + l * 16);
            rA[r] = p[0];
            rB[r] = p[1];
        }

        // ============ init: partial s0 = sum of my 3 rows (packed hadd2) ====
#pragma unroll
        for (int e2 = 0; e2 < 4; e2++) {
            __half2 sa = __hadd2(__hadd2(((__half2*)&rA[0])[e2],
                                         ((__half2*)&rA[1])[e2]),
                                 ((__half2*)&rA[2])[e2]);
            __half2 sb2 = __hadd2(__hadd2(((__half2*)&rB[0])[e2],
                                          ((__half2*)&rB[1])[e2]),
                                  ((__half2*)&rB[2])[e2]);
            sph[wrp * 256 + e2 * 32 + l]       = sa;
            sph[wrp * 256 + (e2 + 4) * 32 + l] = sb2;
        }
        if (wrp == 31) snrm[0 * 32 + l] = 0.f;   // init reduce writes snrm[0]
        __syncthreads();
        // reduce 32 warp-partials (t<256), 1/32, write raw s + atomic nrm
        if (t < 256) {
            float sx = 0.f, sy = 0.f;
#pragma unroll
            for (int w2 = 0; w2 < 32; w2++) {
                float2 u = __half22float2(sph[w2 * 256 + e2R * 32 + fR]);
                sx += u.x; sy += u.y;
            }
            sx *= (1.f / 32.f); sy *= (1.f / 32.f);
            svT[(2 * e2R) * 32 + fR]     = sx;
            svT[(2 * e2R + 1) * 32 + fR] = sy;
            atomicAdd(&snrm[0 * 32 + fR], sx * sx + sy * sy);
        }
        __syncthreads();

        // ============ 2 fused rounds (rows stay in registers) ============
        float b0 = 0.f, b1 = 0.f, b2 = 0.f;
#pragma unroll
        for (int rd = 0; rd < 2; rd++) {
            const int pR = rd;          // read snrm buffer  (init->0, r0->1)
            const int pW = rd ^ 1;      // write snrm buffer (r0->1, r1->0)
            // inline squash scale (replaces t<32 phase + sync)
            float sf = squash_scale(snrm[pR * 32 + l]);
            // pack raw s into half2 registers
            __half2 vh[8];
#pragma unroll
            for (int e2 = 0; e2 < 8; e2++)
                vh[e2] = __floats2half2_rn(svT[(2 * e2) * 32 + l],
                                           svT[(2 * e2 + 1) * 32 + l]);

            __half2 sacc2[8];
#pragma unroll
            for (int e2 = 0; e2 < 8; e2++) sacc2[e2] = __half2half2(__float2half(0.f));

#pragma unroll
            for (int r = 0; r < 3; r++) {
                const __half2* xa = (const __half2*)&rA[r];
                const __half2* xb = (const __half2*)&rB[r];
                // fp16 dot: b-values are ~1e-2 here, fp16 error ~1e-5 abs
                __half2 d2 = __half2half2(__float2half(0.f));
#pragma unroll
                for (int e2 = 0; e2 < 4; e2++) {
                    d2 = __hfma2(vh[e2],     xa[e2], d2);
                    d2 = __hfma2(vh[e2 + 4], xb[e2], d2);
                }
                float2 dd = __half22float2(d2);
                float d = dd.x + dd.y;
                float bcur;
                if (r == 0)      { b0 = fmaf(sf, d, b0); bcur = b0; }
                else if (r == 1) { b1 = fmaf(sf, d, b1); bcur = b1; }
                else             { b2 = fmaf(sf, d, b2); bcur = b2; }
                // warp softmax over f (no max-subtraction: |b| small)
                float ex = __expf(bcur);
                float z = ex;
#pragma unroll
                for (int o = 16; o > 0; o >>= 1)
                    z += __shfl_xor_sync(0xffffffffu, z, o);
                float c = __fdividef(ex, z);
                __half2 c2 = __float2half2_rn(c);
#pragma unroll
                for (int e2 = 0; e2 < 4; e2++) {
                    sacc2[e2]     = __hfma2(c2, xa[e2], sacc2[e2]);
                    sacc2[e2 + 4] = __hfma2(c2, xb[e2], sacc2[e2 + 4]);
                }
            }
#pragma unroll
            for (int e2 = 0; e2 < 8; e2++)
                sph[wrp * 256 + e2 * 32 + l] = sacc2[e2];
            // zero the buffer this round's reduce will write (readers of pW
            // finished >= 2 syncs ago)
            if (wrp == 31) snrm[pW * 32 + l] = 0.f;
            __syncthreads();

            if (t < 256) {
                float sx = 0.f, sy = 0.f;
#pragma unroll
                for (int w2 = 0; w2 < 32; w2++) {
                    float2 u = __half22float2(sph[w2 * 256 + e2R * 32 + fR]);
                    sx += u.x; sy += u.y;
                }
                svT[(2 * e2R) * 32 + fR]     = sx;
                svT[(2 * e2R + 1) * 32 + fR] = sy;
                atomicAdd(&snrm[pW * 32 + fR], sx * sx + sy * sy);
            }
            __syncthreads();
        }

        // ============ output: out[b, w, f, e] = scale(f) * s[f,e] ==========
        // round1's reduce wrote snrm[0]
        if (t < 128) {
            int w = wb >> 2, b = wb & 3;
            int f = t >> 2, e0 = (t & 3) * 4;
            float s = squash_scale(snrm[0 * 32 + f]);
            float4 a;
            a.x = svT[(e0 + 0) * 32 + f] * s;
            a.y = svT[(e0 + 1) * 32 + f] * s;
            a.z = svT[(e0 + 2) * 32 + f] * s;
            a.w = svT[(e0 + 3) * 32 + f] * s;
            *(float4*)(out + (size_t)b * (W_ * COLS_) + (size_t)w * COLS_
                       + f * 16 + e0) = a;
        }
        __syncthreads();
        buf ^= 1;
    }
}

// ---------------------------------------------------------------------------
extern "C" void kernel_launch(void* const* d_in, const int* in_sizes, int n_in,
                              void* d_out, int out_size)
{
    const float* x    = (const float*)d_in[0];
    const float* wgt  = (const float*)d_in[1];
    const float* bias = (const float*)d_in[2];
    float* out = (float*)d_out;

    cudaFuncSetAttribute(routing_kernel,
                         cudaFuncAttributeMaxDynamicSharedMemorySize, SMEM_TOTAL);

    dim3 g1(N_, 32);
    uhat_kernel<<<g1, 256>>>(x, wgt, bias);
    routing_kernel<<<GRID_, 1024, SMEM_TOTAL>>>(out);
}

// round 14
// speedup vs baseline: 1.0886x; 1.0886x over previous
#include <cuda_runtime.h>
#include <cuda_fp16.h>
#include <cstdint>

// Problem constants
#define B_    4
#define L_    1024
#define FP_   32
#define DP_   8
#define F_    32
#define D_    16
#define K_    3
#define W_    1022            // L - K + 1
#define N_    96              // K * FP
#define WB_   4088            // W * B
#define COLS_ 512             // F * D
#define UH_PER_WB 49152       // N * COLS
#define GRID_ 148             // persistent CTAs

// Global scratch for u_hat in fp16: 4088 * 49152 * 2B = 401.8 MB
// 128B-aligned: TMA bulk copy source must be 16B aligned.
__device__ __align__(128) __half g_uhat[(size_t)WB_ * UH_PER_WB];

// ---------------------------------------------------------------------------
// Phase 1: u_hat[wb, n, col] = bias[n,col] + sum_d x[b,w+k,fp,d] * W[n,f,d,e]
// Grid (n=96, tile=32), 256 threads; 2 cols/thread, row-pairs via fma.rn.f32x2.
// ---------------------------------------------------------------------------
__global__ __launch_bounds__(256) void uhat_kernel(const float* __restrict__ x,
                                                   const float* __restrict__ wgt,
                                                   const float* __restrict__ bias)
{
    const int n    = blockIdx.x;      // 0..95
    const int tile = blockIdx.y;      // 0..31
    const int t    = threadIdx.x;
    const int k    = n >> 5;
    const int fp   = n & 31;

    __shared__ float xsT[DP_][128];   // transposed: xsT[d][r]

    {
        int r = t >> 1, q = t & 1;
        int wb = tile * 128 + r;
        float4 v = make_float4(0.f, 0.f, 0.f, 0.f);
        if (wb < WB_) {
            int w = wb >> 2, b = wb & 3;
            const float* p = x + ((size_t)b * (L_ * FP_ * DP_)
                                  + (size_t)(w + k) * (FP_ * DP_)
                                  + fp * DP_ + q * 4);
            v = *(const float4*)p;
        }
        xsT[q * 4 + 0][r] = v.x;
        xsT[q * 4 + 1][r] = v.y;
        xsT[q * 4 + 2][r] = v.z;
        xsT[q * 4 + 3][r] = v.w;
    }

    const int c0 = 2 * t;
    const int f  = c0 >> 4;
    const int e0 = c0 & 15;
    unsigned long long wd0[DP_], wd1[DP_];
    const float* wp = wgt + (size_t)n * (F_ * DP_ * D_) + f * (DP_ * D_) + e0;
#pragma unroll
    for (int d = 0; d < DP_; d++) {
        float2 w2 = *(const float2*)(wp + d * D_);
        asm("mov.b64 %0, {%1, %1};" : "=l"(wd0[d]) : "f"(w2.x));
        asm("mov.b64 %0, {%1, %1};" : "=l"(wd1[d]) : "f"(w2.y));
    }
    float2 bz = *(const float2*)(bias + (size_t)n * COLS_ + c0);
    unsigned long long bia, bib;
    asm("mov.b64 %0, {%1, %1};" : "=l"(bia) : "f"(bz.x));
    asm("mov.b64 %0, {%1, %1};" : "=l"(bib) : "f"(bz.y));

    __syncthreads();

    const int wb0 = tile * 128;
#pragma unroll 1
    for (int r = 0; r < 128; r += 2) {
        unsigned long long acc0 = bia, acc1 = bib;
#pragma unroll
        for (int d = 0; d < DP_; d++) {
            unsigned long long xp = *(const unsigned long long*)&xsT[d][r];
            asm("fma.rn.f32x2 %0, %1, %2, %0;" : "+l"(acc0) : "l"(xp), "l"(wd0[d]));
            asm("fma.rn.f32x2 %0, %1, %2, %0;" : "+l"(acc1) : "l"(xp), "l"(wd1[d]));
        }
        float lo0, hi0, lo1, hi1;
        asm("mov.b64 {%0, %1}, %2;" : "=f"(lo0), "=f"(hi0) : "l"(acc0));
        asm("mov.b64 {%0, %1}, %2;" : "=f"(lo1), "=f"(hi1) : "l"(acc1));
        int wbA = wb0 + r, wbB = wb0 + r + 1;
        if (wbA < WB_)
            *(__half2*)&g_uhat[(size_t)wbA * UH_PER_WB + (size_t)n * COLS_ + c0]
                = __floats2half2_rn(lo0, lo1);
        if (wbB < WB_)
            *(__half2*)&g_uhat[(size_t)wbB * UH_PER_WB + (size_t)n * COLS_ + c0]
                = __floats2half2_rn(hi0, hi1);
    }
}

// ---------------------------------------------------------------------------
// Phase 2: persistent routing, 148 CTAs x 1024 threads (32 warps), double-
// buffered fp16 tile loaded via TMA BULK COPY (cp.async.bulk -> UBLKCP):
// 6 bulk ops per tile instead of 6144 LDGSTS (whose 8-cyc/op SMSP issue rate
// was the R12 bottleneck). Completion via mbarrier expect_tx = 98304 bytes.
// Routing body identical to R12 (best: 141us): warp w owns rows 3w..3w+2
// register-cached, single tile traversal, fp16 hfma2 rounds.
// smem (bytes): su0[98304] su1[98304] sph[32768] svT[2048] ss[128]
//               mbar[16] = 231584
// ---------------------------------------------------------------------------
#define OFF_SU0   0
#define OFF_SU1   98304
#define OFF_SPH   196608
#define OFF_SVT   229376
#define OFF_SS    231424
#define OFF_MBAR  231552
#define SMEM_TOTAL 231584

#define TILE_BYTES 98304u
#define BULK_CHUNK 16384u

__device__ __forceinline__ void mbar_wait(uint32_t mb, uint32_t ph)
{
    asm volatile(
        "{\n\t"
        ".reg .pred P;\n\t"
        "WAIT_%=:\n\t"
        "mbarrier.try_wait.parity.acquire.cta.shared::cta.b64 P, [%0], %1, 0x989680;\n\t"
        "@P bra DONE_%=;\n\t"
        "bra WAIT_%=;\n\t"
        "DONE_%=:\n\t"
        "}"
        :: "r"(mb), "r"(ph) : "memory");
}

__global__ __launch_bounds__(1024, 1) void routing_kernel(float* __restrict__ out)
{
    extern __shared__ __align__(16) unsigned char smem[];
    float*   svT = (float*)(smem + OFF_SVT);   // [16][32] : svT[e*32+f] (raw s)
    float*   ss  = (float*)(smem + OFF_SS);    // [32] squash scale per f
    __half2* sph = (__half2*)(smem + OFF_SPH); // partials [32 warps][8 e2][32 f]

    const int t   = threadIdx.x;
    const int bid = blockIdx.x;
    const uint32_t smem_u32 = (uint32_t)__cvta_generic_to_shared(smem);
    const uint32_t mbar_base = smem_u32 + OFF_MBAR;

    // init both mbarriers (arrive count = 1: the expect_tx arrive)
    if (t == 0) {
        asm volatile("mbarrier.init.shared.b64 [%0], 1;" :: "r"(mbar_base) : "memory");
        asm volatile("mbarrier.init.shared.b64 [%0], 1;" :: "r"(mbar_base + 8) : "memory");
        asm volatile("fence.proxy.async.shared::cta;" ::: "memory");
    }
    __syncthreads();

    // one elected thread issues the whole-tile bulk copy
    auto issue_load = [&](int wb, int bufsel) {
        if (t == 0) {
            uint32_t mb = mbar_base + (uint32_t)bufsel * 8;
            asm volatile("mbarrier.arrive.expect_tx.shared.b64 _, [%0], %1;"
                         :: "r"(mb), "r"(TILE_BYTES) : "memory");
            const char* src = (const char*)(g_uhat + (size_t)wb * UH_PER_WB);
            uint32_t dst = smem_u32 + (bufsel ? OFF_SU1 : OFF_SU0);
#pragma unroll
            for (uint32_t i = 0; i < 6; i++) {
                asm volatile(
                    "cp.async.bulk.shared::cta.global.mbarrier::complete_tx::bytes "
                    "[%0], [%1], %2, [%3];"
                    :: "r"(dst + i * BULK_CHUNK), "l"(src + (size_t)i * BULK_CHUNK),
                       "r"(BULK_CHUNK), "r"(mb)
                    : "memory");
            }
        }
    };

    issue_load(bid, 0);
    int buf = 0;
    uint32_t ph0 = 0, ph1 = 0;

    const int l    = t & 31, wrp = t >> 5;   // lane = f, warp owns rows 3w..3w+2
    const int row0 = wrp * 3;
    const int fR   = t & 31, e2R = t >> 5;   // reduce mapping (valid when t<256)

    for (int wb = bid; wb < WB_; wb += GRID_) {
        const int nxt = wb + GRID_;
        if (nxt < WB_) issue_load(nxt, buf ^ 1);

        // wait for current buffer; flip its phase
        if (buf == 0) { mbar_wait(mbar_base, ph0);     ph0 ^= 1; }
        else          { mbar_wait(mbar_base + 8, ph1); ph1 ^= 1; }

        const __half* suh = (const __half*)(smem + (buf ? OFF_SU1 : OFF_SU0));

        // ---- load my 3 rows ONCE, packed half2 (lane l = f slice, 16 halves)
        uint4 rA[3], rB[3];
#pragma unroll
        for (int r = 0; r < 3; r++) {
            const uint4* p = (const uint4*)(suh + (row0 + r) * 512 + l * 16);
            rA[r] = p[0];
            rB[r] = p[1];
        }

        // ============ init: partial s0 = sum of my 3 rows (packed hadd2) ====
#pragma unroll
        for (int e2 = 0; e2 < 4; e2++) {
            __half2 sa = __hadd2(__hadd2(((__half2*)&rA[0])[e2],
                                         ((__half2*)&rA[1])[e2]),
                                 ((__half2*)&rA[2])[e2]);
            __half2 sb2 = __hadd2(__hadd2(((__half2*)&rB[0])[e2],
                                          ((__half2*)&rB[1])[e2]),
                                  ((__half2*)&rB[2])[e2]);
            sph[wrp * 256 + e2 * 32 + l]       = sa;
            sph[wrp * 256 + (e2 + 4) * 32 + l] = sb2;
        }
        __syncthreads();
        // reduce 32 warp-partials (t<256), apply 1/32, write raw s
        if (t < 256) {
            float sx = 0.f, sy = 0.f;
#pragma unroll
            for (int w2 = 0; w2 < 32; w2++) {
                float2 u = __half22float2(sph[w2 * 256 + e2R * 32 + fR]);
                sx += u.x; sy += u.y;
            }
            svT[(2 * e2R) * 32 + fR]     = sx * (1.f / 32.f);
            svT[(2 * e2R + 1) * 32 + fR] = sy * (1.f / 32.f);
        }
        __syncthreads();
        if (t < 32) {
            float nrm = 0.f;
#pragma unroll
            for (int e = 0; e < 16; e++) {
                float v = svT[e * 32 + t];
                nrm = fmaf(v, v, nrm);
            }
            nrm = fmaxf(nrm, 1e-30f);
            ss[t] = nrm / (1.f + nrm) * rsqrtf(nrm);
        }
        __syncthreads();

        // ============ 2 fused rounds (rows stay in registers) ============
        float b0 = 0.f, b1 = 0.f, b2 = 0.f;
#pragma unroll
        for (int rd = 0; rd < 2; rd++) {
            // pack raw s into half2 registers (8 regs, not 16 fp32)
            __half2 vh[8];
#pragma unroll
            for (int e2 = 0; e2 < 8; e2++)
                vh[e2] = __floats2half2_rn(svT[(2 * e2) * 32 + l],
                                           svT[(2 * e2 + 1) * 32 + l]);
            float sf = ss[l];

            __half2 sacc2[8];
#pragma unroll
            for (int e2 = 0; e2 < 8; e2++) sacc2[e2] = __half2half2(__float2half(0.f));

#pragma unroll
            for (int r = 0; r < 3; r++) {
                const __half2* xa = (const __half2*)&rA[r];
                const __half2* xb = (const __half2*)&rB[r];
                // fp16 dot: b-values are ~1e-2 here, fp16 error ~1e-5 abs
                __half2 d2 = __half2half2(__float2half(0.f));
#pragma unroll
                for (int e2 = 0; e2 < 4; e2++) {
                    d2 = __hfma2(vh[e2],     xa[e2], d2);
                    d2 = __hfma2(vh[e2 + 4], xb[e2], d2);
                }
                float2 dd = __half22float2(d2);
                float d = dd.x + dd.y;
                float bcur;
                if (r == 0)      { b0 = fmaf(sf, d, b0); bcur = b0; }
                else if (r == 1) { b1 = fmaf(sf, d, b1); bcur = b1; }
                else             { b2 = fmaf(sf, d, b2); bcur = b2; }
                // warp softmax over f (no max-subtraction: |b| small)
                float ex = __expf(bcur);
                float z = ex;
#pragma unroll
                for (int o = 16; o > 0; o >>= 1)
                    z += __shfl_xor_sync(0xffffffffu, z, o);
                float c = __fdividef(ex, z);
                __half2 c2 = __float2half2_rn(c);
#pragma unroll
                for (int e2 = 0; e2 < 4; e2++) {
                    sacc2[e2]     = __hfma2(c2, xa[e2], sacc2[e2]);
                    sacc2[e2 + 4] = __hfma2(c2, xb[e2], sacc2[e2 + 4]);
                }
            }
#pragma unroll
            for (int e2 = 0; e2 < 8; e2++)
                sph[wrp * 256 + e2 * 32 + l] = sacc2[e2];
            __syncthreads();

            if (t < 256) {
                float sx = 0.f, sy = 0.f;
#pragma unroll
                for (int w2 = 0; w2 < 32; w2++) {
                    float2 u = __half22float2(sph[w2 * 256 + e2R * 32 + fR]);
                    sx += u.x; sy += u.y;
                }
                svT[(2 * e2R) * 32 + fR]     = sx;
                svT[(2 * e2R + 1) * 32 + fR] = sy;
            }
            __syncthreads();
            if (t < 32) {
                float nrm = 0.f;
#pragma unroll
                for (int e = 0; e < 16; e++) {
                    float v = svT[e * 32 + t];
                    nrm = fmaf(v, v, nrm);
                }
                nrm = fmaxf(nrm, 1e-30f);
                ss[t] = nrm / (1.f + nrm) * rsqrtf(nrm);
            }
            __syncthreads();
        }

        // ============ output: out[b, w, f, e] = ss[f] * s[f,e] ============
        if (t < 128) {
            int w = wb >> 2, b = wb & 3;
            int f = t >> 2, e0 = (t & 3) * 4;
            float s = ss[f];
            float4 a;
            a.x = svT[(e0 + 0) * 32 + f] * s;
            a.y = svT[(e0 + 1) * 32 + f] * s;
            a.z = svT[(e0 + 2) * 32 + f] * s;
            a.w = svT[(e0 + 3) * 32 + f] * s;
            *(float4*)(out + (size_t)b * (W_ * COLS_) + (size_t)w * COLS_
                       + f * 16 + e0) = a;
        }
        __syncthreads();   // buffer-reuse safety for next iteration's issue
        buf ^= 1;
    }
}

// ---------------------------------------------------------------------------
extern "C" void kernel_launch(void* const* d_in, const int* in_sizes, int n_in,
                              void* d_out, int out_size)
{
    const float* x    = (const float*)d_in[0];
    const float* wgt  = (const float*)d_in[1];
    const float* bias = (const float*)d_in[2];
    float* out = (float*)d_out;

    cudaFuncSetAttribute(routing_kernel,
                         cudaFuncAttributeMaxDynamicSharedMemorySize, SMEM_TOTAL);

    dim3 g1(N_, 32);
    uhat_kernel<<<g1, 256>>>(x, wgt, bias);
    routing_kernel<<<GRID_, 1024, SMEM_TOTAL>>>(out);
}